// round 16
// baseline (speedup 1.0000x reference)
#include <cuda_runtime.h>
#include <cuda_fp16.h>
#include <math.h>
#include <stdint.h>

// ---------------------------------------------------------------------------
// Problem constants
// ---------------------------------------------------------------------------
#define BQ    8
#define NTOK  32768
#define NPIX  4096
#define CV    512
#define CFF   2048
#define TT    77
#define TROWS 616
#define NH    8
#define DH    64

// ---------------------------------------------------------------------------
// Scratch (device globals — no allocation allowed)
// ---------------------------------------------------------------------------
__device__ float  g_x   [(size_t)NTOK * CV];
__device__ __half g_xh  [(size_t)NTOK * CV];
__device__ __half g_xl  [(size_t)NTOK * CV];
__device__ float  g_q   [(size_t)NTOK * CV];
__device__ float  g_k   [(size_t)TROWS * CV];
__device__ float  g_v   [(size_t)TROWS * CV];
__device__ int    g_pad [TROWS];
__device__ __half g_atth[(size_t)NTOK * CV];
__device__ float  g_y   [(size_t)NTOK * CV];
__device__ float  g_y2  [(size_t)NTOK * CV];
__device__ __half g_y2h [(size_t)NTOK * CV];
__device__ __half g_hh  [(size_t)NTOK * CFF];
__device__ __half g_wqhT[(size_t)CV * CV];
__device__ __half g_wqlT[(size_t)CV * CV];
__device__ __half g_woT [(size_t)CV * CV];
__device__ __half g_w1T [(size_t)CFF * CV];
__device__ __half g_w2T [(size_t)CV * CFF];

// ---------------------------------------------------------------------------
// Helpers
// ---------------------------------------------------------------------------
__device__ __forceinline__ float warp_sum(float v) {
    #pragma unroll
    for (int o = 16; o; o >>= 1) v += __shfl_xor_sync(0xffffffffu, v, o);
    return v;
}
__device__ __forceinline__ uint32_t smem_u32(const void* p) {
    return (uint32_t)__cvta_generic_to_shared(p);
}
__device__ __forceinline__ void cp16_s(uint32_t s, const void* g) {
    asm volatile("cp.async.ca.shared.global [%0], [%1], 16;" :: "r"(s), "l"(g));
}
__device__ __forceinline__ void cp_commit() {
    asm volatile("cp.async.commit_group;");
}
__device__ __forceinline__ void ffma2(uint64_t& d, uint64_t a, uint64_t b) {
    asm("fma.rn.f32x2 %0, %1, %2, %0;" : "+l"(d) : "l"(a), "l"(b));
}
__device__ __forceinline__ uint64_t pack_dup(float a) {
    uint64_t p;
    asm("mov.b64 %0, {%1, %1};" : "=l"(p) : "f"(a));
    return p;
}
__device__ __forceinline__ void unpack2(uint64_t p, float& lo, float& hi) {
    asm("mov.b64 {%0, %1}, %2;" : "=f"(lo), "=f"(hi) : "l"(p));
}
__device__ __forceinline__ void ldsm_x4(uint32_t r[4], uint32_t addr) {
    asm volatile("ldmatrix.sync.aligned.m8n8.x4.shared.b16 {%0,%1,%2,%3}, [%4];"
                 : "=r"(r[0]), "=r"(r[1]), "=r"(r[2]), "=r"(r[3]) : "r"(addr));
}
__device__ __forceinline__ void ldsm_x2(uint32_t r[2], uint32_t addr) {
    asm volatile("ldmatrix.sync.aligned.m8n8.x2.shared.b16 {%0,%1}, [%2];"
                 : "=r"(r[0]), "=r"(r[1]) : "r"(addr));
}
__device__ __forceinline__ void mma_f16(float d[4],
                                        uint32_t a0, uint32_t a1, uint32_t a2, uint32_t a3,
                                        uint32_t b0, uint32_t b1) {
    asm volatile("mma.sync.aligned.m16n8k16.row.col.f32.f16.f16.f32 "
                 "{%0,%1,%2,%3}, {%4,%5,%6,%7}, {%8,%9}, {%0,%1,%2,%3};"
                 : "+f"(d[0]), "+f"(d[1]), "+f"(d[2]), "+f"(d[3])
                 : "r"(a0), "r"(a1), "r"(a2), "r"(a3), "r"(b0), "r"(b1));
}
// order-preserving float<->u32 bijection (monotone increasing)
__device__ __forceinline__ uint32_t f2ord(float f) {
    const uint32_t b = __float_as_uint(f);
    return (b & 0x80000000u) ? ~b : (b | 0x80000000u);
}
__device__ __forceinline__ float ord2f(uint32_t o) {
    const uint32_t b = (o & 0x80000000u) ? (o ^ 0x80000000u) : ~o;
    return __uint_as_float(b);
}

// ---------------------------------------------------------------------------
// LayerNorm: fp32 out + optional half out + optional lo-half (split)
// ---------------------------------------------------------------------------
__global__ void ln_kernel(const float* __restrict__ in,
                          const float* __restrict__ g,
                          const float* __restrict__ b,
                          float* __restrict__ out,
                          __half* __restrict__ out_h,
                          __half* __restrict__ out_l)
{
    __shared__ float sh[8];
    const int r = blockIdx.x, tid = threadIdx.x;
    const float4 v = ((const float4*)(in + (size_t)r * CV))[tid];
    float s  = v.x + v.y + v.z + v.w;
    float ss = v.x*v.x + v.y*v.y + v.z*v.z + v.w*v.w;
    float ws = warp_sum(s), wss = warp_sum(ss);
    if ((tid & 31) == 0) { sh[tid >> 5] = ws; sh[4 + (tid >> 5)] = wss; }
    __syncthreads();
    float tot = 0.f, tots = 0.f;
    #pragma unroll
    for (int i = 0; i < 4; i++) { tot += sh[i]; tots += sh[4 + i]; }
    const float mean = tot * (1.0f / CV);
    const float var  = tots * (1.0f / CV) - mean * mean;
    const float rstd = rsqrtf(var + 1e-5f);
    const float4 gg = ((const float4*)g)[tid];
    const float4 bb = ((const float4*)b)[tid];
    float o[4];
    o[0] = (v.x - mean) * rstd * gg.x + bb.x;
    o[1] = (v.y - mean) * rstd * gg.y + bb.y;
    o[2] = (v.z - mean) * rstd * gg.z + bb.z;
    o[3] = (v.w - mean) * rstd * gg.w + bb.w;
    ((float4*)(out + (size_t)r * CV))[tid] = make_float4(o[0], o[1], o[2], o[3]);
    if (out_h) {
        __half h[4];
        #pragma unroll
        for (int i = 0; i < 4; i++) h[i] = __float2half_rn(o[i]);
        ((uint2*)(out_h + (size_t)r * CV))[tid] = *(uint2*)h;
        if (out_l) {
            __half l[4];
            #pragma unroll
            for (int i = 0; i < 4; i++)
                l[i] = __float2half_rn(o[i] - __half2float(h[i]));
            ((uint2*)(out_l + (size_t)r * CV))[tid] = *(uint2*)l;
        }
    }
}

// ---------------------------------------------------------------------------
// Pad mask
// ---------------------------------------------------------------------------
__global__ void padmask_kernel(const float* __restrict__ txt, int* __restrict__ pad)
{
    __shared__ float sh[4];
    const int r = blockIdx.x, tid = threadIdx.x;
    const float4 v = ((const float4*)(txt + (size_t)r * CV))[tid];
    float s = fabsf(v.x) + fabsf(v.y) + fabsf(v.z) + fabsf(v.w);
    float ws = warp_sum(s);
    if ((tid & 31) == 0) sh[tid >> 5] = ws;
    __syncthreads();
    if (tid == 0) {
        float tot = sh[0] + sh[1] + sh[2] + sh[3];
        pad[r] = (tot <= 1e-6f) ? 1 : 0;
    }
}

// ---------------------------------------------------------------------------
// Per-head L2 norm (K only; Q norm fused into attention)
// ---------------------------------------------------------------------------
__global__ void l2norm_kernel(float* __restrict__ q, int nrows,
                              const float* __restrict__ ls_ptr, int do_scale)
{
    const int w = (blockIdx.x * blockDim.x + threadIdx.x) >> 5;
    const int lane = threadIdx.x & 31;
    if (w >= nrows) return;
    float* p = q + (size_t)w * DH;
    const float a = p[lane], b = p[lane + 32];
    float ss = warp_sum(a * a + b * b);
    const float n = sqrtf(ss);
    float inv = 1.0f / fmaxf(n, 1e-6f);
    if (do_scale) {
        float ls = ls_ptr[0];
        ls = fminf(fmaxf(ls, -2.0f), 2.0f);
        inv *= expf(ls) * 0.125f;
    }
    p[lane]      = a * inv;
    p[lane + 32] = b * inv;
}

// ---------------------------------------------------------------------------
// Weight transposes: fp32 W[R][C] -> half WT[C][R]; split variant for wq
// ---------------------------------------------------------------------------
__global__ void transpose_h_kernel(const float* __restrict__ in,
                                   __half* __restrict__ out, int R, int Ccols)
{
    __shared__ float t[32][33];
    const int bx = blockIdx.x * 32, by = blockIdx.y * 32;
    const int x = threadIdx.x, y0 = threadIdx.y;
    #pragma unroll
    for (int dy = 0; dy < 32; dy += 8)
        t[y0 + dy][x] = in[(size_t)(by + y0 + dy) * Ccols + bx + x];
    __syncthreads();
    #pragma unroll
    for (int dy = 0; dy < 32; dy += 8)
        out[(size_t)(bx + y0 + dy) * R + by + x] = __float2half_rn(t[x][y0 + dy]);
}

__global__ void transpose_split_kernel(const float* __restrict__ in,
                                       __half* __restrict__ outh,
                                       __half* __restrict__ outl, int R, int Ccols)
{
    __shared__ float t[32][33];
    const int bx = blockIdx.x * 32, by = blockIdx.y * 32;
    const int x = threadIdx.x, y0 = threadIdx.y;
    #pragma unroll
    for (int dy = 0; dy < 32; dy += 8)
        t[y0 + dy][x] = in[(size_t)(by + y0 + dy) * Ccols + bx + x];
    __syncthreads();
    #pragma unroll
    for (int dy = 0; dy < 32; dy += 8) {
        const float w = t[x][y0 + dy];
        const __half hh = __float2half_rn(w);
        outh[(size_t)(bx + y0 + dy) * R + by + x] = hh;
        outl[(size_t)(bx + y0 + dy) * R + by + x] =
            __float2half_rn(w - __half2float(hh));
    }
}

// ---------------------------------------------------------------------------
// FP32 SIMT SGEMM (K/V projections — exact fp32)
// ---------------------------------------------------------------------------
#define GBM 128
#define GBN 128
#define GBK 8

__device__ __forceinline__
void sgemm_body(const float* __restrict__ A, const float* __restrict__ W,
                const float* __restrict__ bias, float* __restrict__ C,
                int M, int N, int K, int bm, int bn)
{
    __shared__ float As[GBK][GBM];
    __shared__ float Bs[GBK][GBN];

    const int tid = threadIdx.x;
    const int ty = tid >> 4;
    const int tx = tid & 15;
    const int arow = tid >> 1;
    const int acol = (tid & 1) * 4;
    const int brow = tid >> 5;
    const int bcol = (tid & 31) * 4;

    uint64_t acc2[8][4];
    #pragma unroll
    for (int i = 0; i < 8; i++)
        #pragma unroll
        for (int j = 0; j < 4; j++) acc2[i][j] = 0ull;

    for (int k0 = 0; k0 < K; k0 += GBK) {
        float4 av = make_float4(0.f, 0.f, 0.f, 0.f);
        if (bm + arow < M)
            av = *(const float4*)&A[(size_t)(bm + arow) * K + k0 + acol];
        As[acol + 0][arow] = av.x;
        As[acol + 1][arow] = av.y;
        As[acol + 2][arow] = av.z;
        As[acol + 3][arow] = av.w;
        *(float4*)&Bs[brow][bcol] =
            *(const float4*)&W[(size_t)(k0 + brow) * N + bn + bcol];
        __syncthreads();

        #pragma unroll
        for (int k = 0; k < GBK; k++) {
            const float4 a0 = *(const float4*)&As[k][ty * 8];
            const float4 a1 = *(const float4*)&As[k][ty * 8 + 4];
            const float ra[8] = {a0.x, a0.y, a0.z, a0.w, a1.x, a1.y, a1.z, a1.w};
            uint64_t rb[4];
            rb[0] = *(const uint64_t*)&Bs[k][tx * 8 + 0];
            rb[1] = *(const uint64_t*)&Bs[k][tx * 8 + 2];
            rb[2] = *(const uint64_t*)&Bs[k][tx * 8 + 4];
            rb[3] = *(const uint64_t*)&Bs[k][tx * 8 + 6];
            #pragma unroll
            for (int i = 0; i < 8; i++) {
                const uint64_t pa = pack_dup(ra[i]);
                #pragma unroll
                for (int j = 0; j < 4; j++)
                    ffma2(acc2[i][j], pa, rb[j]);
            }
        }
        __syncthreads();
    }

    #pragma unroll
    for (int i = 0; i < 8; i++) {
        const int m = bm + ty * 8 + i;
        if (m >= M) break;
        #pragma unroll
        for (int j = 0; j < 4; j++) {
            const int n = bn + tx * 8 + 2 * j;
            float lo, hi;
            unpack2(acc2[i][j], lo, hi);
            C[(size_t)m * N + n]     = lo + bias[n];
            C[(size_t)m * N + n + 1] = hi + bias[n + 1];
        }
    }
}

__global__ __launch_bounds__(256, 2)
void kv_sgemm_kernel(const float* __restrict__ A,
                     const float* __restrict__ Wk, const float* __restrict__ bk_,
                     float* __restrict__ Ck,
                     const float* __restrict__ Wv, const float* __restrict__ bv_,
                     float* __restrict__ Cv_,
                     int M, int N, int K)
{
    const float* W = (blockIdx.z == 0) ? Wk : Wv;
    const float* bias = (blockIdx.z == 0) ? bk_ : bv_;
    float* C = (blockIdx.z == 0) ? Ck : Cv_;
    sgemm_body(A, W, bias, C, M, N, K, blockIdx.y * GBM, blockIdx.x * GBN);
}

// ---------------------------------------------------------------------------
// FP16 tensor-core GEMM: 3-stage cp.async, ldmatrix (R13 configuration).
// ---------------------------------------------------------------------------
#define HLD 40
#define H_A_WORDS (128 * HLD)
#define H_STAGE_HALVES (2 * 128 * HLD)
#define HSTAGES 3
#define HGEMM_SMEM (HSTAGES * H_STAGE_HALVES * 2)

template<int EPI>
__global__ __launch_bounds__(256, 2)
void hgemm_kernel(const __half* __restrict__ A, const __half* __restrict__ WT,
                  const float* __restrict__ bias, const float* __restrict__ resid,
                  const float* __restrict__ alpha_p,
                  void* __restrict__ Cv, int M, int N, int K)
{
    extern __shared__ __half hsm[];

    const int tid  = threadIdx.x;
    const int bm   = blockIdx.y * 128;
    const int bn   = blockIdx.x * 128;
    const int w    = tid >> 5;
    const int lane = tid & 31;
    const int grp  = lane >> 2;
    const int ctg  = lane & 3;
    const int wm   = (w & 1) * 64;
    const int wn   = (w >> 1) * 32;
    const int a_ld_row = lane & 15;
    const int a_ld_col = (lane >> 4) << 3;
    const int b_ld_row = lane & 7;
    const int b_ld_col = ((lane >> 3) & 1) << 3;

    float acc[4][4][4];
    #pragma unroll
    for (int i = 0; i < 4; i++)
        #pragma unroll
        for (int j = 0; j < 4; j++)
            #pragma unroll
            for (int c = 0; c < 4; c++) acc[i][j][c] = 0.f;

    const int ntiles = K >> 5;

    auto issue_tile = [&](int kt, int st) {
        const int k0 = kt << 5;
        __half* As = hsm + st * H_STAGE_HALVES;
        __half* Bs = As + H_A_WORDS;
        #pragma unroll
        for (int j = 0; j < 2; j++) {
            const int u = tid + 256 * j;
            const int r = u >> 2, sg = (u & 3) * 8;
            cp16_s(smem_u32(&As[r * HLD + sg]), &A[(size_t)(bm + r) * K + k0 + sg]);
        }
        #pragma unroll
        for (int j = 0; j < 2; j++) {
            const int u = tid + 256 * j;
            const int r = u >> 2, sg = (u & 3) * 8;
            cp16_s(smem_u32(&Bs[r * HLD + sg]), &WT[(size_t)(bn + r) * K + k0 + sg]);
        }
        cp_commit();
    };

    issue_tile(0, 0);
    if (ntiles > 1) issue_tile(1, 1);

    for (int kt = 0; kt < ntiles; kt++) {
        if (kt == ntiles - 1) asm volatile("cp.async.wait_group 0;" ::: "memory");
        else                  asm volatile("cp.async.wait_group 1;" ::: "memory");
        __syncthreads();

        if (kt + 2 < ntiles) issue_tile(kt + 2, (kt + 2) % HSTAGES);

        const int st = kt % HSTAGES;
        const __half* As = hsm + st * H_STAGE_HALVES;
        const __half* Bs = As + H_A_WORDS;

        #pragma unroll
        for (int k16 = 0; k16 < 32; k16 += 16) {
            uint32_t af[4][4];
            #pragma unroll
            for (int mt = 0; mt < 4; mt++)
                ldsm_x4(af[mt], smem_u32(
                    &As[(wm + mt * 16 + a_ld_row) * HLD + k16 + a_ld_col]));
            uint32_t bf[4][2];
            #pragma unroll
            for (int nt = 0; nt < 4; nt++)
                ldsm_x2(bf[nt], smem_u32(
                    &Bs[(wn + nt * 8 + b_ld_row) * HLD + k16 + b_ld_col]));
            #pragma unroll
            for (int mt = 0; mt < 4; mt++)
                #pragma unroll
                for (int nt = 0; nt < 4; nt++)
                    mma_f16(acc[mt][nt], af[mt][0], af[mt][1], af[mt][2], af[mt][3],
                            bf[nt][0], bf[nt][1]);
        }
    }

    const float alpha = (EPI == 2) ? alpha_p[0] : 1.0f;
    #pragma unroll
    for (int mt = 0; mt < 4; mt++) {
        #pragma unroll
        for (int hf = 0; hf < 2; hf++) {
            const int m = bm + wm + mt * 16 + grp + hf * 8;
            #pragma unroll
            for (int nt = 0; nt < 4; nt++) {
                const int n = bn + wn + nt * 8 + 2 * ctg;
                float c0 = acc[mt][nt][2 * hf + 0] + bias[n];
                float c1 = acc[mt][nt][2 * hf + 1] + bias[n + 1];
                const size_t idx = (size_t)m * N + n;
                if (EPI == 1) {
                    c0 = 0.5f * c0 * (1.0f + erff(c0 * 0.70710678118654752f));
                    c1 = 0.5f * c1 * (1.0f + erff(c1 * 0.70710678118654752f));
                    __half2 hv = __floats2half2_rn(c0, c1);
                    *(__half2*)&((__half*)Cv)[idx] = hv;
                } else if (EPI == 2) {
                    const float2 rr = *(const float2*)&resid[idx];
                    *(float2*)&((float*)Cv)[idx] =
                        make_float2(rr.x + alpha * c0, rr.y + alpha * c1);
                } else {
                    const float2 rr = *(const float2*)&resid[idx];
                    *(float2*)&((float*)Cv)[idx] = make_float2(rr.x + c0, rr.y + c1);
                }
            }
        }
    }
}

// ---------------------------------------------------------------------------
// Fused split-fp16 Q projection (2-stage, R13 configuration)
// ---------------------------------------------------------------------------
#define QTILE_HALVES (128 * HLD)
#define QSTAGE_HALVES (4 * QTILE_HALVES)
#define QG_SMEM (2 * QSTAGE_HALVES * 2)

__global__ __launch_bounds__(256, 1)
void qgemm_kernel(const __half* __restrict__ Ah, const __half* __restrict__ Al,
                  const __half* __restrict__ Wh, const __half* __restrict__ Wl,
                  const float* __restrict__ bias, float* __restrict__ C,
                  int M, int N, int K)
{
    extern __shared__ __half hsm[];

    const int tid  = threadIdx.x;
    const int bm   = blockIdx.y * 128;
    const int bn   = blockIdx.x * 128;
    const int w    = tid >> 5;
    const int lane = tid & 31;
    const int grp  = lane >> 2;
    const int ctg  = lane & 3;
    const int wm   = (w & 1) * 64;
    const int wn   = (w >> 1) * 32;
    const int a_ld_row = lane & 15;
    const int a_ld_col = (lane >> 4) << 3;
    const int b_ld_row = lane & 7;
    const int b_ld_col = ((lane >> 3) & 1) << 3;

    float acc[4][4][4];
    #pragma unroll
    for (int i = 0; i < 4; i++)
        #pragma unroll
        for (int j = 0; j < 4; j++)
            #pragma unroll
            for (int c = 0; c < 4; c++) acc[i][j][c] = 0.f;

    const int ntiles = K >> 5;

    auto issue_tile = [&](int kt, int st) {
        const int k0 = kt << 5;
        __half* base = hsm + st * QSTAGE_HALVES;
        const int r = tid >> 1, sg = (tid & 1) * 16;
        #pragma unroll
        for (int half2x = 0; half2x < 2; half2x++) {
            const int rr = r, ss = sg + half2x * 8;
            cp16_s(smem_u32(&base[0 * QTILE_HALVES + rr * HLD + ss]),
                   &Ah[(size_t)(bm + rr) * K + k0 + ss]);
            cp16_s(smem_u32(&base[1 * QTILE_HALVES + rr * HLD + ss]),
                   &Al[(size_t)(bm + rr) * K + k0 + ss]);
            cp16_s(smem_u32(&base[2 * QTILE_HALVES + rr * HLD + ss]),
                   &Wh[(size_t)(bn + rr) * K + k0 + ss]);
            cp16_s(smem_u32(&base[3 * QTILE_HALVES + rr * HLD + ss]),
                   &Wl[(size_t)(bn + rr) * K + k0 + ss]);
        }
        cp_commit();
    };

    issue_tile(0, 0);

    for (int kt = 0; kt < ntiles; kt++) {
        asm volatile("cp.async.wait_group 0;" ::: "memory");
        __syncthreads();
        if (kt + 1 < ntiles) issue_tile(kt + 1, (kt + 1) & 1);

        const __half* base = hsm + (kt & 1) * QSTAGE_HALVES;
        const __half* Ahs = base;
        const __half* Als = base + QTILE_HALVES;
        const __half* Whs = base + 2 * QTILE_HALVES;
        const __half* Wls = base + 3 * QTILE_HALVES;

        #pragma unroll
        for (int k16 = 0; k16 < 32; k16 += 16) {
            uint32_t ah[4][4], al[4][4];
            #pragma unroll
            for (int mt = 0; mt < 4; mt++) {
                const int off = (wm + mt * 16 + a_ld_row) * HLD + k16 + a_ld_col;
                ldsm_x4(ah[mt], smem_u32(&Ahs[off]));
                ldsm_x4(al[mt], smem_u32(&Als[off]));
            }
            uint32_t bh[4][2], bl[4][2];
            #pragma unroll
            for (int nt = 0; nt < 4; nt++) {
                const int off = (wn + nt * 8 + b_ld_row) * HLD + k16 + b_ld_col;
                ldsm_x2(bh[nt], smem_u32(&Whs[off]));
                ldsm_x2(bl[nt], smem_u32(&Wls[off]));
            }
            #pragma unroll
            for (int mt = 0; mt < 4; mt++)
                #pragma unroll
                for (int nt = 0; nt < 4; nt++) {
                    mma_f16(acc[mt][nt], ah[mt][0], ah[mt][1], ah[mt][2], ah[mt][3],
                            bh[nt][0], bh[nt][1]);
                    mma_f16(acc[mt][nt], ah[mt][0], ah[mt][1], ah[mt][2], ah[mt][3],
                            bl[nt][0], bl[nt][1]);
                    mma_f16(acc[mt][nt], al[mt][0], al[mt][1], al[mt][2], al[mt][3],
                            bh[nt][0], bh[nt][1]);
                }
        }
    }

    #pragma unroll
    for (int mt = 0; mt < 4; mt++) {
        #pragma unroll
        for (int hf = 0; hf < 2; hf++) {
            const int m = bm + wm + mt * 16 + grp + hf * 8;
            #pragma unroll
            for (int nt = 0; nt < 4; nt++) {
                const int n = bn + wn + nt * 8 + 2 * ctg;
                const float c0 = acc[mt][nt][2 * hf + 0] + bias[n];
                const float c1 = acc[mt][nt][2 * hf + 1] + bias[n + 1];
                *(float2*)&C[(size_t)m * N + n] = make_float2(c0, c1);
            }
        }
    }
}

// ---------------------------------------------------------------------------
// Attention v4: fused Q l2norm, batched sim, REDUX-based interleaved top-5,
// sparse AV. Selection semantics bit-identical (monotone ord-space).
// ---------------------------------------------------------------------------
#define LDK 68

__global__ __launch_bounds__(256)
void attn_kernel(const float* __restrict__ q, const float* __restrict__ k,
                 const float* __restrict__ v, const int* __restrict__ pad,
                 const float* __restrict__ ls_ptr,
                 __half* __restrict__ out)
{
    __shared__ __align__(16) float   ks[TT][LDK];
    __shared__ __align__(16) float   qs[8][8][64];
    __shared__ __align__(16) __half2 vsh[TT][33];
    __shared__ int     ps[TT];
    __shared__ int     s_t[8][16];
    __shared__ float   s_w[8][16];

    const int b = blockIdx.x >> 3;
    const int h = blockIdx.x & 7;
    const int tid = threadIdx.x;
    const int w = tid >> 5, lane = tid & 31;

    float ls = ls_ptr[0];
    ls = fminf(fmaxf(ls, -2.0f), 2.0f);
    const float qscale = expf(ls) * 0.125f;

    for (int i = tid; i < TT * DH; i += 256) {
        const int t = i >> 6, d = i & 63;
        ks[t][d] = k[(size_t)(b * TT + t) * CV + h * DH + d];
    }
    for (int i = tid; i < TT * 32; i += 256) {
        const int t = i >> 5, d2 = i & 31;
        const float2 vv = *(const float2*)&v[(size_t)(b * TT + t) * CV + h * DH + 2 * d2];
        vsh[t][d2] = __floats2half2_rn(vv.x, vv.y);
    }
    if (tid < TT) ps[tid] = pad[b * TT + tid];
    __syncthreads();

    // load this warp's 8 q rows with fused per-head l2norm * scale
    const int n0 = blockIdx.y * 64 + w * 8;
    #pragma unroll
    for (int r = 0; r < 8; r++) {
        const size_t qb = ((size_t)b * NPIX + n0 + r) * CV + h * DH;
        const float a = q[qb + lane];
        const float bq_ = q[qb + lane + 32];
        const float ss = warp_sum(a * a + bq_ * bq_);
        const float inv = qscale / fmaxf(sqrtf(ss), 1e-6f);
        qs[w][r][lane]      = a * inv;
        qs[w][r][lane + 32] = bq_ * inv;
    }
    __syncwarp();

    const int t0 = lane, t1 = lane + 32, t2 = lane + 64;
    const int t2r = (t2 < TT) ? t2 : 0;
    float acc[3][8];
    #pragma unroll
    for (int j = 0; j < 3; j++)
        #pragma unroll
        for (int r = 0; r < 8; r++) acc[j][r] = 0.f;

    #pragma unroll
    for (int i = 0; i < 64; i += 4) {
        const float4 k0 = *(const float4*)&ks[t0][i];
        const float4 k1 = *(const float4*)&ks[t1][i];
        const float4 k2 = *(const float4*)&ks[t2r][i];
        #pragma unroll
        for (int r = 0; r < 8; r++) {
            const float4 qv = *(const float4*)&qs[w][r][i];
            acc[0][r] += k0.x * qv.x + k0.y * qv.y + k0.z * qv.z + k0.w * qv.w;
            acc[1][r] += k1.x * qv.x + k1.y * qv.y + k1.z * qv.z + k1.w * qv.w;
            acc[2][r] += k2.x * qv.x + k2.y * qv.y + k2.z * qv.z + k2.w * qv.w;
        }
    }

    const bool v0 = !ps[t0];
    const bool v1 = !ps[t1];
    const bool v2ok = (t2 < TT) && !ps[t2r];

    // ord-space sims (monotone map; -inf for invalid)
    const uint32_t ORDNI = f2ord(-INFINITY);
    uint32_t ov[3][8];
    #pragma unroll
    for (int r = 0; r < 8; r++) {
        ov[0][r] = v0   ? f2ord(acc[0][r]) : ORDNI;
        ov[1][r] = v1   ? f2ord(acc[1][r]) : ORDNI;
        ov[2][r] = v2ok ? f2ord(acc[2][r]) : ORDNI;
    }

    // interleaved exact top-5 (tie-correct), REDUX warp max
    uint32_t used = 0;                    // bit (4*r + j)
    uint32_t thr_ord[8], m_ord[8];
    #pragma unroll
    for (int iter = 0; iter < 5; iter++) {
        #pragma unroll
        for (int r = 0; r < 8; r++) {
            uint32_t lb = ORDNI; int li = -1;
            #pragma unroll
            for (int j = 0; j < 3; j++)
                if (!((used >> (4 * r + j)) & 1u) && ov[j][r] > lb) {
                    lb = ov[j][r]; li = j;
                }
            const uint32_t best = __reduce_max_sync(0xffffffffu, lb);
            const unsigned bal = __ballot_sync(0xffffffffu, (lb == best) && (li >= 0));
            const int leader = __ffs(bal) - 1;
            if (lane == leader) used |= (1u << (4 * r + li));
            if (iter == 0) m_ord[r] = best;
            thr_ord[r] = best;
        }
    }

    #pragma unroll
    for (int r = 0; r < 8; r++) {
        const bool alive = (m_ord[r] > ORDNI);
        const float m = ord2f(m_ord[r]);

        bool keep[3]; float wv[3]; float lsum = 0.f;
        #pragma unroll
        for (int j = 0; j < 3; j++) {
            keep[j] = alive && (ov[j][r] >= thr_ord[r]) && (ov[j][r] > ORDNI);
            wv[j] = keep[j] ? expf(ord2f(ov[j][r]) - m) : 0.f;
            lsum += wv[j];
        }
        const float psum = warp_sum(lsum);
        const float inv = alive ? (1.0f / psum) : 0.f;

        int cnt = 0;
        #pragma unroll
        for (int j = 0; j < 3; j++) {
            const unsigned bal = __ballot_sync(0xffffffffu, keep[j]);
            if (keep[j]) {
                const int idx = cnt + __popc(bal & ((1u << lane) - 1u));
                if (idx < 16) {
                    s_t[w][idx] = lane + 32 * j;
                    s_w[w][idx] = wv[j] * inv;
                }
            }
            cnt += __popc(bal);
        }
        __syncwarp();
        if (cnt > 16) cnt = 16;

        float a0 = 0.f, a1 = 0.f;
        for (int i2 = 0; i2 < cnt; i2++) {
            const float a = s_w[w][i2];
            const int t = s_t[w][i2];
            const float2 vv = __half22float2(vsh[t][lane]);
            a0 += a * vv.x;
            a1 += a * vv.y;
        }
        const size_t qb = ((size_t)b * NPIX + n0 + r) * CV + h * DH;
        *(__half2*)&out[qb + 2 * lane] = __floats2half2_rn(a0, a1);
        __syncwarp();
    }
}

// ---------------------------------------------------------------------------
// Launcher — multi-stream overlap (KV chain + transposes alongside Q chain)
// ---------------------------------------------------------------------------
static cudaStream_t s_kv = nullptr;
static cudaStream_t s_w  = nullptr;
static cudaEvent_t  ev_fork  = nullptr;
static cudaEvent_t  ev_kv    = nullptr;
static cudaEvent_t  ev_w     = nullptr;

extern "C" void kernel_launch(void* const* d_in, const int* in_sizes, int n_in,
                              void* d_out, int out_size)
{
    const float* vis  = (const float*)d_in[0];
    const float* txt  = (const float*)d_in[1];
    const float* ln1g = (const float*)d_in[2];
    const float* ln1b = (const float*)d_in[3];
    const float* wq   = (const float*)d_in[4];
    const float* bq   = (const float*)d_in[5];
    const float* wk   = (const float*)d_in[6];
    const float* bk   = (const float*)d_in[7];
    const float* wv   = (const float*)d_in[8];
    const float* bv   = (const float*)d_in[9];
    const float* wo   = (const float*)d_in[10];
    const float* bo   = (const float*)d_in[11];
    const float* ln2g = (const float*)d_in[12];
    const float* ln2b = (const float*)d_in[13];
    const float* w1   = (const float*)d_in[14];
    const float* b1   = (const float*)d_in[15];
    const float* w2   = (const float*)d_in[16];
    const float* b2   = (const float*)d_in[17];
    const float* alpha = (const float*)d_in[18];
    const float* lsc   = (const float*)d_in[19];
    float* out = (float*)d_out;

    float *px, *pq, *pk, *pv, *py, *py2;
    __half *pxh, *pxl, *patth, *py2h, *phh, *pwqhT, *pwqlT, *pwoT, *pw1T, *pw2T;
    int* ppad;
    cudaGetSymbolAddress((void**)&px,    g_x);
    cudaGetSymbolAddress((void**)&pxh,   g_xh);
    cudaGetSymbolAddress((void**)&pxl,   g_xl);
    cudaGetSymbolAddress((void**)&pq,    g_q);
    cudaGetSymbolAddress((void**)&pk,    g_k);
    cudaGetSymbolAddress((void**)&pv,    g_v);
    cudaGetSymbolAddress((void**)&ppad,  g_pad);
    cudaGetSymbolAddress((void**)&patth, g_atth);
    cudaGetSymbolAddress((void**)&py,    g_y);
    cudaGetSymbolAddress((void**)&py2,   g_y2);
    cudaGetSymbolAddress((void**)&py2h,  g_y2h);
    cudaGetSymbolAddress((void**)&phh,   g_hh);
    cudaGetSymbolAddress((void**)&pwqhT, g_wqhT);
    cudaGetSymbolAddress((void**)&pwqlT, g_wqlT);
    cudaGetSymbolAddress((void**)&pwoT,  g_woT);
    cudaGetSymbolAddress((void**)&pw1T,  g_w1T);
    cudaGetSymbolAddress((void**)&pw2T,  g_w2T);

    cudaFuncSetAttribute(hgemm_kernel<1>, cudaFuncAttributeMaxDynamicSharedMemorySize, HGEMM_SMEM);
    cudaFuncSetAttribute(hgemm_kernel<2>, cudaFuncAttributeMaxDynamicSharedMemorySize, HGEMM_SMEM);
    cudaFuncSetAttribute(hgemm_kernel<3>, cudaFuncAttributeMaxDynamicSharedMemorySize, HGEMM_SMEM);
    cudaFuncSetAttribute(qgemm_kernel,    cudaFuncAttributeMaxDynamicSharedMemorySize, QG_SMEM);

    if (!s_kv) {
        cudaStreamCreateWithFlags(&s_kv, cudaStreamNonBlocking);
        cudaStreamCreateWithFlags(&s_w,  cudaStreamNonBlocking);
        cudaEventCreateWithFlags(&ev_fork, cudaEventDisableTiming);
        cudaEventCreateWithFlags(&ev_kv,   cudaEventDisableTiming);
        cudaEventCreateWithFlags(&ev_w,    cudaEventDisableTiming);
    }

    cudaEventRecord(ev_fork, 0);
    cudaStreamWaitEvent(s_kv, ev_fork, 0);
    cudaStreamWaitEvent(s_w,  ev_fork, 0);

    // --- side stream s_w: weight transposes ---
    transpose_split_kernel<<<dim3(CV / 32, CV / 32), dim3(32, 8), 0, s_w>>>(wq, pwqhT, pwqlT, CV, CV);
    transpose_h_kernel<<<dim3(CV / 32, CV / 32), dim3(32, 8), 0, s_w>>>(wo, pwoT, CV, CV);
    transpose_h_kernel<<<dim3(CFF / 32, CV / 32), dim3(32, 8), 0, s_w>>>(w1, pw1T, CV, CFF);
    transpose_h_kernel<<<dim3(CV / 32, CFF / 32), dim3(32, 8), 0, s_w>>>(w2, pw2T, CFF, CV);
    cudaEventRecord(ev_w, s_w);

    // --- side stream s_kv: K/V projections + K l2norm + pad mask ---
    kv_sgemm_kernel<<<dim3(CV / GBN, (TROWS + GBM - 1) / GBM, 2), 256, 0, s_kv>>>(
        txt, wk, bk, pk, wv, bv, pv, TROWS, CV, CV);
    l2norm_kernel<<<TROWS, 256, 0, s_kv>>>(pk, TROWS * NH, nullptr, 0);
    padmask_kernel<<<TROWS, 128, 0, s_kv>>>(txt, ppad);
    cudaEventRecord(ev_kv, s_kv);

    // --- main stream: LN1 -> Q chain ---
    ln_kernel<<<NTOK, 128>>>(vis, ln1g, ln1b, px, pxh, pxl);

    cudaStreamWaitEvent(0, ev_w, 0);
    qgemm_kernel<<<dim3(CV / 128, NTOK / 128), 256, QG_SMEM>>>(
        pxh, pxl, pwqhT, pwqlT, bq, pq, NTOK, CV, CV);

    cudaStreamWaitEvent(0, ev_kv, 0);
    attn_kernel<<<dim3(BQ * NH, NPIX / 64), 256>>>(pq, pk, pv, ppad, lsc, patth);

    // 5. O-proj (fp16 TC): y = x + alpha*(att@wo + bo)
    hgemm_kernel<2><<<dim3(CV / 128, NTOK / 128), 256, HGEMM_SMEM>>>(
        patth, pwoT, bo, px, alpha, py, NTOK, CV, CV);

    // 6. LN2 (fp32 + half)
    ln_kernel<<<NTOK, 128>>>(py, ln2g, ln2b, py2, py2h, nullptr);

    // 7. MLP (fp16 TC): h = half(gelu(y2@w1 + b1)); out = y2 + h@w2 + b2
    hgemm_kernel<1><<<dim3(CFF / 128, NTOK / 128), 256, HGEMM_SMEM>>>(
        py2h, pw1T, b1, nullptr, nullptr, phh, NTOK, CFF, CV);
    hgemm_kernel<3><<<dim3(CV / 128, NTOK / 128), 256, HGEMM_SMEM>>>(
        phh, pw2T, b2, py2, nullptr, out, NTOK, CV, CFF);
}

// round 17
// speedup vs baseline: 1.0114x; 1.0114x over previous
#include <cuda_runtime.h>
#include <cuda_fp16.h>
#include <math.h>
#include <stdint.h>

// ---------------------------------------------------------------------------
// Problem constants
// ---------------------------------------------------------------------------
#define BQ    8
#define NTOK  32768
#define NPIX  4096
#define CV    512
#define CFF   2048
#define TT    77
#define TROWS 616
#define NH    8
#define DH    64

// ---------------------------------------------------------------------------
// Scratch (device globals — no allocation allowed)
// ---------------------------------------------------------------------------
__device__ float  g_x   [(size_t)NTOK * CV];
__device__ __half g_xh  [(size_t)NTOK * CV];
__device__ __half g_xl  [(size_t)NTOK * CV];
__device__ float  g_q   [(size_t)NTOK * CV];
__device__ float  g_k   [(size_t)TROWS * CV];
__device__ float  g_v   [(size_t)TROWS * CV];
__device__ int    g_pad [TROWS];
__device__ __half g_atth[(size_t)NTOK * CV];
__device__ float  g_y   [(size_t)NTOK * CV];
__device__ float  g_y2  [(size_t)NTOK * CV];
__device__ __half g_y2h [(size_t)NTOK * CV];
__device__ __half g_hh  [(size_t)NTOK * CFF];
__device__ __half g_wqhT[(size_t)CV * CV];
__device__ __half g_wqlT[(size_t)CV * CV];
__device__ __half g_woT [(size_t)CV * CV];
__device__ __half g_w1T [(size_t)CFF * CV];
__device__ __half g_w2T [(size_t)CV * CFF];

// ---------------------------------------------------------------------------
// Helpers
// ---------------------------------------------------------------------------
__device__ __forceinline__ float warp_sum(float v) {
    #pragma unroll
    for (int o = 16; o; o >>= 1) v += __shfl_xor_sync(0xffffffffu, v, o);
    return v;
}
__device__ __forceinline__ float warp_max(float v) {
    #pragma unroll
    for (int o = 16; o; o >>= 1) v = fmaxf(v, __shfl_xor_sync(0xffffffffu, v, o));
    return v;
}
__device__ __forceinline__ uint32_t smem_u32(const void* p) {
    return (uint32_t)__cvta_generic_to_shared(p);
}
__device__ __forceinline__ void cp16_s(uint32_t s, const void* g) {
    asm volatile("cp.async.ca.shared.global [%0], [%1], 16;" :: "r"(s), "l"(g));
}
__device__ __forceinline__ void cp_commit() {
    asm volatile("cp.async.commit_group;");
}
__device__ __forceinline__ void ffma2(uint64_t& d, uint64_t a, uint64_t b) {
    asm("fma.rn.f32x2 %0, %1, %2, %0;" : "+l"(d) : "l"(a), "l"(b));
}
__device__ __forceinline__ uint64_t pack_dup(float a) {
    uint64_t p;
    asm("mov.b64 %0, {%1, %1};" : "=l"(p) : "f"(a));
    return p;
}
__device__ __forceinline__ void unpack2(uint64_t p, float& lo, float& hi) {
    asm("mov.b64 {%0, %1}, %2;" : "=f"(lo), "=f"(hi) : "l"(p));
}
__device__ __forceinline__ void ldsm_x4(uint32_t r[4], uint32_t addr) {
    asm volatile("ldmatrix.sync.aligned.m8n8.x4.shared.b16 {%0,%1,%2,%3}, [%4];"
                 : "=r"(r[0]), "=r"(r[1]), "=r"(r[2]), "=r"(r[3]) : "r"(addr));
}
__device__ __forceinline__ void ldsm_x2(uint32_t r[2], uint32_t addr) {
    asm volatile("ldmatrix.sync.aligned.m8n8.x2.shared.b16 {%0,%1}, [%2];"
                 : "=r"(r[0]), "=r"(r[1]) : "r"(addr));
}
__device__ __forceinline__ void mma_f16(float d[4],
                                        uint32_t a0, uint32_t a1, uint32_t a2, uint32_t a3,
                                        uint32_t b0, uint32_t b1) {
    asm volatile("mma.sync.aligned.m16n8k16.row.col.f32.f16.f16.f32 "
                 "{%0,%1,%2,%3}, {%4,%5,%6,%7}, {%8,%9}, {%0,%1,%2,%3};"
                 : "+f"(d[0]), "+f"(d[1]), "+f"(d[2]), "+f"(d[3])
                 : "r"(a0), "r"(a1), "r"(a2), "r"(a3), "r"(b0), "r"(b1));
}

// ---------------------------------------------------------------------------
// LayerNorm: fp32 out + optional half out + optional lo-half (split)
// ---------------------------------------------------------------------------
__global__ void ln_kernel(const float* __restrict__ in,
                          const float* __restrict__ g,
                          const float* __restrict__ b,
                          float* __restrict__ out,
                          __half* __restrict__ out_h,
                          __half* __restrict__ out_l)
{
    __shared__ float sh[8];
    const int r = blockIdx.x, tid = threadIdx.x;
    const float4 v = ((const float4*)(in + (size_t)r * CV))[tid];
    float s  = v.x + v.y + v.z + v.w;
    float ss = v.x*v.x + v.y*v.y + v.z*v.z + v.w*v.w;
    float ws = warp_sum(s), wss = warp_sum(ss);
    if ((tid & 31) == 0) { sh[tid >> 5] = ws; sh[4 + (tid >> 5)] = wss; }
    __syncthreads();
    float tot = 0.f, tots = 0.f;
    #pragma unroll
    for (int i = 0; i < 4; i++) { tot += sh[i]; tots += sh[4 + i]; }
    const float mean = tot * (1.0f / CV);
    const float var  = tots * (1.0f / CV) - mean * mean;
    const float rstd = rsqrtf(var + 1e-5f);
    const float4 gg = ((const float4*)g)[tid];
    const float4 bb = ((const float4*)b)[tid];
    float o[4];
    o[0] = (v.x - mean) * rstd * gg.x + bb.x;
    o[1] = (v.y - mean) * rstd * gg.y + bb.y;
    o[2] = (v.z - mean) * rstd * gg.z + bb.z;
    o[3] = (v.w - mean) * rstd * gg.w + bb.w;
    ((float4*)(out + (size_t)r * CV))[tid] = make_float4(o[0], o[1], o[2], o[3]);
    if (out_h) {
        __half h[4];
        #pragma unroll
        for (int i = 0; i < 4; i++) h[i] = __float2half_rn(o[i]);
        ((uint2*)(out_h + (size_t)r * CV))[tid] = *(uint2*)h;
        if (out_l) {
            __half l[4];
            #pragma unroll
            for (int i = 0; i < 4; i++)
                l[i] = __float2half_rn(o[i] - __half2float(h[i]));
            ((uint2*)(out_l + (size_t)r * CV))[tid] = *(uint2*)l;
        }
    }
}

// ---------------------------------------------------------------------------
// Pad mask
// ---------------------------------------------------------------------------
__global__ void padmask_kernel(const float* __restrict__ txt, int* __restrict__ pad)
{
    __shared__ float sh[4];
    const int r = blockIdx.x, tid = threadIdx.x;
    const float4 v = ((const float4*)(txt + (size_t)r * CV))[tid];
    float s = fabsf(v.x) + fabsf(v.y) + fabsf(v.z) + fabsf(v.w);
    float ws = warp_sum(s);
    if ((tid & 31) == 0) sh[tid >> 5] = ws;
    __syncthreads();
    if (tid == 0) {
        float tot = sh[0] + sh[1] + sh[2] + sh[3];
        pad[r] = (tot <= 1e-6f) ? 1 : 0;
    }
}

// ---------------------------------------------------------------------------
// Per-head L2 norm
// ---------------------------------------------------------------------------
__global__ void l2norm_kernel(float* __restrict__ q, int nrows,
                              const float* __restrict__ ls_ptr, int do_scale)
{
    const int w = (blockIdx.x * blockDim.x + threadIdx.x) >> 5;
    const int lane = threadIdx.x & 31;
    if (w >= nrows) return;
    float* p = q + (size_t)w * DH;
    const float a = p[lane], b = p[lane + 32];
    float ss = warp_sum(a * a + b * b);
    const float n = sqrtf(ss);
    float inv = 1.0f / fmaxf(n, 1e-6f);
    if (do_scale) {
        float ls = ls_ptr[0];
        ls = fminf(fmaxf(ls, -2.0f), 2.0f);
        inv *= expf(ls) * 0.125f;
    }
    p[lane]      = a * inv;
    p[lane + 32] = b * inv;
}

// ---------------------------------------------------------------------------
// Weight transposes: fp32 W[R][C] -> half WT[C][R]; split variant for wq
// ---------------------------------------------------------------------------
__global__ void transpose_h_kernel(const float* __restrict__ in,
                                   __half* __restrict__ out, int R, int Ccols)
{
    __shared__ float t[32][33];
    const int bx = blockIdx.x * 32, by = blockIdx.y * 32;
    const int x = threadIdx.x, y0 = threadIdx.y;
    #pragma unroll
    for (int dy = 0; dy < 32; dy += 8)
        t[y0 + dy][x] = in[(size_t)(by + y0 + dy) * Ccols + bx + x];
    __syncthreads();
    #pragma unroll
    for (int dy = 0; dy < 32; dy += 8)
        out[(size_t)(bx + y0 + dy) * R + by + x] = __float2half_rn(t[x][y0 + dy]);
}

__global__ void transpose_split_kernel(const float* __restrict__ in,
                                       __half* __restrict__ outh,
                                       __half* __restrict__ outl, int R, int Ccols)
{
    __shared__ float t[32][33];
    const int bx = blockIdx.x * 32, by = blockIdx.y * 32;
    const int x = threadIdx.x, y0 = threadIdx.y;
    #pragma unroll
    for (int dy = 0; dy < 32; dy += 8)
        t[y0 + dy][x] = in[(size_t)(by + y0 + dy) * Ccols + bx + x];
    __syncthreads();
    #pragma unroll
    for (int dy = 0; dy < 32; dy += 8) {
        const float w = t[x][y0 + dy];
        const __half hh = __float2half_rn(w);
        outh[(size_t)(bx + y0 + dy) * R + by + x] = hh;
        outl[(size_t)(bx + y0 + dy) * R + by + x] =
            __float2half_rn(w - __half2float(hh));
    }
}

// ---------------------------------------------------------------------------
// FP32 SIMT SGEMM (K/V projections — exact fp32)
// ---------------------------------------------------------------------------
#define GBM 128
#define GBN 128
#define GBK 8

__device__ __forceinline__
void sgemm_body(const float* __restrict__ A, const float* __restrict__ W,
                const float* __restrict__ bias, float* __restrict__ C,
                int M, int N, int K, int bm, int bn)
{
    __shared__ float As[GBK][GBM];
    __shared__ float Bs[GBK][GBN];

    const int tid = threadIdx.x;
    const int ty = tid >> 4;
    const int tx = tid & 15;
    const int arow = tid >> 1;
    const int acol = (tid & 1) * 4;
    const int brow = tid >> 5;
    const int bcol = (tid & 31) * 4;

    uint64_t acc2[8][4];
    #pragma unroll
    for (int i = 0; i < 8; i++)
        #pragma unroll
        for (int j = 0; j < 4; j++) acc2[i][j] = 0ull;

    for (int k0 = 0; k0 < K; k0 += GBK) {
        float4 av = make_float4(0.f, 0.f, 0.f, 0.f);
        if (bm + arow < M)
            av = *(const float4*)&A[(size_t)(bm + arow) * K + k0 + acol];
        As[acol + 0][arow] = av.x;
        As[acol + 1][arow] = av.y;
        As[acol + 2][arow] = av.z;
        As[acol + 3][arow] = av.w;
        *(float4*)&Bs[brow][bcol] =
            *(const float4*)&W[(size_t)(k0 + brow) * N + bn + bcol];
        __syncthreads();

        #pragma unroll
        for (int k = 0; k < GBK; k++) {
            const float4 a0 = *(const float4*)&As[k][ty * 8];
            const float4 a1 = *(const float4*)&As[k][ty * 8 + 4];
            const float ra[8] = {a0.x, a0.y, a0.z, a0.w, a1.x, a1.y, a1.z, a1.w};
            uint64_t rb[4];
            rb[0] = *(const uint64_t*)&Bs[k][tx * 8 + 0];
            rb[1] = *(const uint64_t*)&Bs[k][tx * 8 + 2];
            rb[2] = *(const uint64_t*)&Bs[k][tx * 8 + 4];
            rb[3] = *(const uint64_t*)&Bs[k][tx * 8 + 6];
            #pragma unroll
            for (int i = 0; i < 8; i++) {
                const uint64_t pa = pack_dup(ra[i]);
                #pragma unroll
                for (int j = 0; j < 4; j++)
                    ffma2(acc2[i][j], pa, rb[j]);
            }
        }
        __syncthreads();
    }

    #pragma unroll
    for (int i = 0; i < 8; i++) {
        const int m = bm + ty * 8 + i;
        if (m >= M) break;
        #pragma unroll
        for (int j = 0; j < 4; j++) {
            const int n = bn + tx * 8 + 2 * j;
            float lo, hi;
            unpack2(acc2[i][j], lo, hi);
            C[(size_t)m * N + n]     = lo + bias[n];
            C[(size_t)m * N + n + 1] = hi + bias[n + 1];
        }
    }
}

__global__ __launch_bounds__(256, 2)
void kv_sgemm_kernel(const float* __restrict__ A,
                     const float* __restrict__ Wk, const float* __restrict__ bk_,
                     float* __restrict__ Ck,
                     const float* __restrict__ Wv, const float* __restrict__ bv_,
                     float* __restrict__ Cv_,
                     int M, int N, int K)
{
    const float* W = (blockIdx.z == 0) ? Wk : Wv;
    const float* bias = (blockIdx.z == 0) ? bk_ : bv_;
    float* C = (blockIdx.z == 0) ? Ck : Cv_;
    sgemm_body(A, W, bias, C, M, N, K, blockIdx.y * GBM, blockIdx.x * GBN);
}

// ---------------------------------------------------------------------------
// FP16 tensor-core GEMM (mma.sync m16n8k16, fp32 accum), cp.async 3-stage,
// ldmatrix fragment loads.
// ---------------------------------------------------------------------------
#define HLD 40
#define H_A_WORDS (128 * HLD)
#define H_STAGE_HALVES (2 * 128 * HLD)
#define HSTAGES 3
#define HGEMM_SMEM (HSTAGES * H_STAGE_HALVES * 2)

template<int EPI>
__global__ __launch_bounds__(256, 2)
void hgemm_kernel(const __half* __restrict__ A, const __half* __restrict__ WT,
                  const float* __restrict__ bias, const float* __restrict__ resid,
                  const float* __restrict__ alpha_p,
                  void* __restrict__ Cv, int M, int N, int K)
{
    extern __shared__ __half hsm[];

    const int tid  = threadIdx.x;
    const int bm   = blockIdx.y * 128;
    const int bn   = blockIdx.x * 128;
    const int w    = tid >> 5;
    const int lane = tid & 31;
    const int grp  = lane >> 2;
    const int ctg  = lane & 3;
    const int wm   = (w & 1) * 64;
    const int wn   = (w >> 1) * 32;
    const int a_ld_row = lane & 15;
    const int a_ld_col = (lane >> 4) << 3;
    const int b_ld_row = lane & 7;
    const int b_ld_col = ((lane >> 3) & 1) << 3;

    float acc[4][4][4];
    #pragma unroll
    for (int i = 0; i < 4; i++)
        #pragma unroll
        for (int j = 0; j < 4; j++)
            #pragma unroll
            for (int c = 0; c < 4; c++) acc[i][j][c] = 0.f;

    const int ntiles = K >> 5;

    auto issue_tile = [&](int kt, int st) {
        const int k0 = kt << 5;
        __half* As = hsm + st * H_STAGE_HALVES;
        __half* Bs = As + H_A_WORDS;
        #pragma unroll
        for (int j = 0; j < 2; j++) {
            const int u = tid + 256 * j;
            const int r = u >> 2, sg = (u & 3) * 8;
            cp16_s(smem_u32(&As[r * HLD + sg]), &A[(size_t)(bm + r) * K + k0 + sg]);
        }
        #pragma unroll
        for (int j = 0; j < 2; j++) {
            const int u = tid + 256 * j;
            const int r = u >> 2, sg = (u & 3) * 8;
            cp16_s(smem_u32(&Bs[r * HLD + sg]), &WT[(size_t)(bn + r) * K + k0 + sg]);
        }
        cp_commit();
    };

    issue_tile(0, 0);
    if (ntiles > 1) issue_tile(1, 1);

    for (int kt = 0; kt < ntiles; kt++) {
        if (kt == ntiles - 1) asm volatile("cp.async.wait_group 0;" ::: "memory");
        else                  asm volatile("cp.async.wait_group 1;" ::: "memory");
        __syncthreads();

        if (kt + 2 < ntiles) issue_tile(kt + 2, (kt + 2) % HSTAGES);

        const int st = kt % HSTAGES;
        const __half* As = hsm + st * H_STAGE_HALVES;
        const __half* Bs = As + H_A_WORDS;

        #pragma unroll
        for (int k16 = 0; k16 < 32; k16 += 16) {
            uint32_t af[4][4];
            #pragma unroll
            for (int mt = 0; mt < 4; mt++)
                ldsm_x4(af[mt], smem_u32(
                    &As[(wm + mt * 16 + a_ld_row) * HLD + k16 + a_ld_col]));
            uint32_t bf[4][2];
            #pragma unroll
            for (int nt = 0; nt < 4; nt++)
                ldsm_x2(bf[nt], smem_u32(
                    &Bs[(wn + nt * 8 + b_ld_row) * HLD + k16 + b_ld_col]));
            #pragma unroll
            for (int mt = 0; mt < 4; mt++)
                #pragma unroll
                for (int nt = 0; nt < 4; nt++)
                    mma_f16(acc[mt][nt], af[mt][0], af[mt][1], af[mt][2], af[mt][3],
                            bf[nt][0], bf[nt][1]);
        }
    }

    const float alpha = (EPI == 2) ? alpha_p[0] : 1.0f;
    #pragma unroll
    for (int mt = 0; mt < 4; mt++) {
        #pragma unroll
        for (int hf = 0; hf < 2; hf++) {
            const int m = bm + wm + mt * 16 + grp + hf * 8;
            #pragma unroll
            for (int nt = 0; nt < 4; nt++) {
                const int n = bn + wn + nt * 8 + 2 * ctg;
                float c0 = acc[mt][nt][2 * hf + 0] + bias[n];
                float c1 = acc[mt][nt][2 * hf + 1] + bias[n + 1];
                const size_t idx = (size_t)m * N + n;
                if (EPI == 1) {
                    c0 = 0.5f * c0 * (1.0f + erff(c0 * 0.70710678118654752f));
                    c1 = 0.5f * c1 * (1.0f + erff(c1 * 0.70710678118654752f));
                    __half2 hv = __floats2half2_rn(c0, c1);
                    *(__half2*)&((__half*)Cv)[idx] = hv;
                } else if (EPI == 2) {
                    const float2 rr = *(const float2*)&resid[idx];
                    *(float2*)&((float*)Cv)[idx] =
                        make_float2(rr.x + alpha * c0, rr.y + alpha * c1);
                } else {
                    const float2 rr = *(const float2*)&resid[idx];
                    *(float2*)&((float*)Cv)[idx] = make_float2(rr.x + c0, rr.y + c1);
                }
            }
        }
    }
}

// ---------------------------------------------------------------------------
// Fused split-fp16 Q projection: Q = xh@whT + xh@wlT + xl@whT + bias
// ---------------------------------------------------------------------------
#define QTILE_HALVES (128 * HLD)
#define QSTAGE_HALVES (4 * QTILE_HALVES)
#define QG_SMEM (2 * QSTAGE_HALVES * 2)

__global__ __launch_bounds__(256, 1)
void qgemm_kernel(const __half* __restrict__ Ah, const __half* __restrict__ Al,
                  const __half* __restrict__ Wh, const __half* __restrict__ Wl,
                  const float* __restrict__ bias, float* __restrict__ C,
                  int M, int N, int K)
{
    extern __shared__ __half hsm[];

    const int tid  = threadIdx.x;
    const int bm   = blockIdx.y * 128;
    const int bn   = blockIdx.x * 128;
    const int w    = tid >> 5;
    const int lane = tid & 31;
    const int grp  = lane >> 2;
    const int ctg  = lane & 3;
    const int wm   = (w & 1) * 64;
    const int wn   = (w >> 1) * 32;
    const int a_ld_row = lane & 15;
    const int a_ld_col = (lane >> 4) << 3;
    const int b_ld_row = lane & 7;
    const int b_ld_col = ((lane >> 3) & 1) << 3;

    float acc[4][4][4];
    #pragma unroll
    for (int i = 0; i < 4; i++)
        #pragma unroll
        for (int j = 0; j < 4; j++)
            #pragma unroll
            for (int c = 0; c < 4; c++) acc[i][j][c] = 0.f;

    const int ntiles = K >> 5;

    auto issue_tile = [&](int kt, int st) {
        const int k0 = kt << 5;
        __half* base = hsm + st * QSTAGE_HALVES;
        const int r = tid >> 1, sg = (tid & 1) * 16;
        #pragma unroll
        for (int half2x = 0; half2x < 2; half2x++) {
            const int rr = r, ss = sg + half2x * 8;
            cp16_s(smem_u32(&base[0 * QTILE_HALVES + rr * HLD + ss]),
                   &Ah[(size_t)(bm + rr) * K + k0 + ss]);
            cp16_s(smem_u32(&base[1 * QTILE_HALVES + rr * HLD + ss]),
                   &Al[(size_t)(bm + rr) * K + k0 + ss]);
            cp16_s(smem_u32(&base[2 * QTILE_HALVES + rr * HLD + ss]),
                   &Wh[(size_t)(bn + rr) * K + k0 + ss]);
            cp16_s(smem_u32(&base[3 * QTILE_HALVES + rr * HLD + ss]),
                   &Wl[(size_t)(bn + rr) * K + k0 + ss]);
        }
        cp_commit();
    };

    issue_tile(0, 0);

    for (int kt = 0; kt < ntiles; kt++) {
        asm volatile("cp.async.wait_group 0;" ::: "memory");
        __syncthreads();
        if (kt + 1 < ntiles) issue_tile(kt + 1, (kt + 1) & 1);

        const __half* base = hsm + (kt & 1) * QSTAGE_HALVES;
        const __half* Ahs = base;
        const __half* Als = base + QTILE_HALVES;
        const __half* Whs = base + 2 * QTILE_HALVES;
        const __half* Wls = base + 3 * QTILE_HALVES;

        #pragma unroll
        for (int k16 = 0; k16 < 32; k16 += 16) {
            uint32_t ah[4][4], al[4][4];
            #pragma unroll
            for (int mt = 0; mt < 4; mt++) {
                const int off = (wm + mt * 16 + a_ld_row) * HLD + k16 + a_ld_col;
                ldsm_x4(ah[mt], smem_u32(&Ahs[off]));
                ldsm_x4(al[mt], smem_u32(&Als[off]));
            }
            uint32_t bh[4][2], bl[4][2];
            #pragma unroll
            for (int nt = 0; nt < 4; nt++) {
                const int off = (wn + nt * 8 + b_ld_row) * HLD + k16 + b_ld_col;
                ldsm_x2(bh[nt], smem_u32(&Whs[off]));
                ldsm_x2(bl[nt], smem_u32(&Wls[off]));
            }
            #pragma unroll
            for (int mt = 0; mt < 4; mt++)
                #pragma unroll
                for (int nt = 0; nt < 4; nt++) {
                    mma_f16(acc[mt][nt], ah[mt][0], ah[mt][1], ah[mt][2], ah[mt][3],
                            bh[nt][0], bh[nt][1]);
                    mma_f16(acc[mt][nt], ah[mt][0], ah[mt][1], ah[mt][2], ah[mt][3],
                            bl[nt][0], bl[nt][1]);
                    mma_f16(acc[mt][nt], al[mt][0], al[mt][1], al[mt][2], al[mt][3],
                            bh[nt][0], bh[nt][1]);
                }
        }
    }

    #pragma unroll
    for (int mt = 0; mt < 4; mt++) {
        #pragma unroll
        for (int hf = 0; hf < 2; hf++) {
            const int m = bm + wm + mt * 16 + grp + hf * 8;
            #pragma unroll
            for (int nt = 0; nt < 4; nt++) {
                const int n = bn + wn + nt * 8 + 2 * ctg;
                const float c0 = acc[mt][nt][2 * hf + 0] + bias[n];
                const float c1 = acc[mt][nt][2 * hf + 1] + bias[n + 1];
                *(float2*)&C[(size_t)m * N + n] = make_float2(c0, c1);
            }
        }
    }
}

// ---------------------------------------------------------------------------
// Attention v2: batched sim (8 rows/warp share K reads) + sparse top-5 AV.
// ---------------------------------------------------------------------------
#define LDK 68

__global__ __launch_bounds__(256)
void attn_kernel(const float* __restrict__ q, const float* __restrict__ k,
                 const float* __restrict__ v, const int* __restrict__ pad,
                 __half* __restrict__ out)
{
    __shared__ __align__(16) float   ks[TT][LDK];
    __shared__ __align__(16) float   qs[8][8][64];
    __shared__ __align__(16) __half2 vsh[TT][33];
    __shared__ int     ps[TT];
    __shared__ int     s_t[8][16];
    __shared__ float   s_w[8][16];

    const int b = blockIdx.x >> 3;
    const int h = blockIdx.x & 7;
    const int tid = threadIdx.x;
    const int w = tid >> 5, lane = tid & 31;

    for (int i = tid; i < TT * DH; i += 256) {
        const int t = i >> 6, d = i & 63;
        ks[t][d] = k[(size_t)(b * TT + t) * CV + h * DH + d];
    }
    for (int i = tid; i < TT * 32; i += 256) {
        const int t = i >> 5, d2 = i & 31;
        const float2 vv = *(const float2*)&v[(size_t)(b * TT + t) * CV + h * DH + 2 * d2];
        vsh[t][d2] = __floats2half2_rn(vv.x, vv.y);
    }
    if (tid < TT) ps[tid] = pad[b * TT + tid];
    __syncthreads();

    const int n0 = blockIdx.y * 64 + w * 8;
    #pragma unroll
    for (int r = 0; r < 8; r++) {
        const size_t qb = ((size_t)b * NPIX + n0 + r) * CV + h * DH;
        qs[w][r][lane]      = q[qb + lane];
        qs[w][r][lane + 32] = q[qb + lane + 32];
    }
    __syncwarp();

    const int t0 = lane, t1 = lane + 32, t2 = lane + 64;
    const int t2r = (t2 < TT) ? t2 : 0;
    float acc[3][8];
    #pragma unroll
    for (int j = 0; j < 3; j++)
        #pragma unroll
        for (int r = 0; r < 8; r++) acc[j][r] = 0.f;

    #pragma unroll
    for (int i = 0; i < 64; i += 4) {
        const float4 k0 = *(const float4*)&ks[t0][i];
        const float4 k1 = *(const float4*)&ks[t1][i];
        const float4 k2 = *(const float4*)&ks[t2r][i];
        #pragma unroll
        for (int r = 0; r < 8; r++) {
            const float4 qv = *(const float4*)&qs[w][r][i];
            acc[0][r] += k0.x * qv.x + k0.y * qv.y + k0.z * qv.z + k0.w * qv.w;
            acc[1][r] += k1.x * qv.x + k1.y * qv.y + k1.z * qv.z + k1.w * qv.w;
            acc[2][r] += k2.x * qv.x + k2.y * qv.y + k2.z * qv.z + k2.w * qv.w;
        }
    }

    const bool v0 = !ps[t0];
    const bool v1 = !ps[t1];
    const bool v2ok = (t2 < TT) && !ps[t2r];

    #pragma unroll
    for (int r = 0; r < 8; r++) {
        float vals[3];
        vals[0] = v0   ? acc[0][r] : -INFINITY;
        vals[1] = v1   ? acc[1][r] : -INFINITY;
        vals[2] = v2ok ? acc[2][r] : -INFINITY;

        unsigned used = 0;
        float thr = -INFINITY, m = -INFINITY;
        #pragma unroll 1
        for (int iter = 0; iter < 5; iter++) {
            float lb = -INFINITY; int li = -1;
            #pragma unroll
            for (int j = 0; j < 3; j++)
                if (!((used >> j) & 1u) && vals[j] > lb) { lb = vals[j]; li = j; }
            const float best = warp_max(lb);
            const unsigned bal = __ballot_sync(0xffffffffu, (lb == best) && (li >= 0));
            const int leader = __ffs(bal) - 1;
            if (lane == leader) used |= (1u << li);
            if (iter == 0) m = best;
            thr = best;
        }

        const bool alive = (m > -INFINITY);
        bool keep[3]; float wv[3]; float lsum = 0.f;
        #pragma unroll
        for (int j = 0; j < 3; j++) {
            keep[j] = alive && (vals[j] >= thr) && (vals[j] > -INFINITY);
            wv[j] = keep[j] ? expf(vals[j] - m) : 0.f;
            lsum += wv[j];
        }
        const float psum = warp_sum(lsum);
        const float inv = alive ? (1.0f / psum) : 0.f;

        int cnt = 0;
        #pragma unroll
        for (int j = 0; j < 3; j++) {
            const unsigned bal = __ballot_sync(0xffffffffu, keep[j]);
            if (keep[j]) {
                const int idx = cnt + __popc(bal & ((1u << lane) - 1u));
                if (idx < 16) {
                    s_t[w][idx] = lane + 32 * j;
                    s_w[w][idx] = wv[j] * inv;
                }
            }
            cnt += __popc(bal);
        }
        __syncwarp();
        if (cnt > 16) cnt = 16;

        float a0 = 0.f, a1 = 0.f;
        for (int i2 = 0; i2 < cnt; i2++) {
            const float a = s_w[w][i2];
            const int t = s_t[w][i2];
            const float2 vv = __half22float2(vsh[t][lane]);
            a0 += a * vv.x;
            a1 += a * vv.y;
        }
        const size_t qb = ((size_t)b * NPIX + n0 + r) * CV + h * DH;
        *(__half2*)&out[qb + 2 * lane] = __floats2half2_rn(a0, a1);
        __syncwarp();
    }
}

// ---------------------------------------------------------------------------
// Launcher — multi-stream: KV chain and weight transposes overlap the Q chain.
// ---------------------------------------------------------------------------
static cudaStream_t s_kv = nullptr;
static cudaStream_t s_w  = nullptr;
static cudaEvent_t  ev_fork  = nullptr;
static cudaEvent_t  ev_kv    = nullptr;
static cudaEvent_t  ev_w     = nullptr;

extern "C" void kernel_launch(void* const* d_in, const int* in_sizes, int n_in,
                              void* d_out, int out_size)
{
    const float* vis  = (const float*)d_in[0];
    const float* txt  = (const float*)d_in[1];
    const float* ln1g = (const float*)d_in[2];
    const float* ln1b = (const float*)d_in[3];
    const float* wq   = (const float*)d_in[4];
    const float* bq   = (const float*)d_in[5];
    const float* wk   = (const float*)d_in[6];
    const float* bk   = (const float*)d_in[7];
    const float* wv   = (const float*)d_in[8];
    const float* bv   = (const float*)d_in[9];
    const float* wo   = (const float*)d_in[10];
    const float* bo   = (const float*)d_in[11];
    const float* ln2g = (const float*)d_in[12];
    const float* ln2b = (const float*)d_in[13];
    const float* w1   = (const float*)d_in[14];
    const float* b1   = (const float*)d_in[15];
    const float* w2   = (const float*)d_in[16];
    const float* b2   = (const float*)d_in[17];
    const float* alpha = (const float*)d_in[18];
    const float* lsc   = (const float*)d_in[19];
    float* out = (float*)d_out;

    float *px, *pq, *pk, *pv, *py, *py2;
    __half *pxh, *pxl, *patth, *py2h, *phh, *pwqhT, *pwqlT, *pwoT, *pw1T, *pw2T;
    int* ppad;
    cudaGetSymbolAddress((void**)&px,    g_x);
    cudaGetSymbolAddress((void**)&pxh,   g_xh);
    cudaGetSymbolAddress((void**)&pxl,   g_xl);
    cudaGetSymbolAddress((void**)&pq,    g_q);
    cudaGetSymbolAddress((void**)&pk,    g_k);
    cudaGetSymbolAddress((void**)&pv,    g_v);
    cudaGetSymbolAddress((void**)&ppad,  g_pad);
    cudaGetSymbolAddress((void**)&patth, g_atth);
    cudaGetSymbolAddress((void**)&py,    g_y);
    cudaGetSymbolAddress((void**)&py2,   g_y2);
    cudaGetSymbolAddress((void**)&py2h,  g_y2h);
    cudaGetSymbolAddress((void**)&phh,   g_hh);
    cudaGetSymbolAddress((void**)&pwqhT, g_wqhT);
    cudaGetSymbolAddress((void**)&pwqlT, g_wqlT);
    cudaGetSymbolAddress((void**)&pwoT,  g_woT);
    cudaGetSymbolAddress((void**)&pw1T,  g_w1T);
    cudaGetSymbolAddress((void**)&pw2T,  g_w2T);

    cudaFuncSetAttribute(hgemm_kernel<1>, cudaFuncAttributeMaxDynamicSharedMemorySize, HGEMM_SMEM);
    cudaFuncSetAttribute(hgemm_kernel<2>, cudaFuncAttributeMaxDynamicSharedMemorySize, HGEMM_SMEM);
    cudaFuncSetAttribute(hgemm_kernel<3>, cudaFuncAttributeMaxDynamicSharedMemorySize, HGEMM_SMEM);
    cudaFuncSetAttribute(qgemm_kernel,    cudaFuncAttributeMaxDynamicSharedMemorySize, QG_SMEM);

    if (!s_kv) {
        cudaStreamCreateWithFlags(&s_kv, cudaStreamNonBlocking);
        cudaStreamCreateWithFlags(&s_w,  cudaStreamNonBlocking);
        cudaEventCreateWithFlags(&ev_fork, cudaEventDisableTiming);
        cudaEventCreateWithFlags(&ev_kv,   cudaEventDisableTiming);
        cudaEventCreateWithFlags(&ev_w,    cudaEventDisableTiming);
    }

    // fork side streams off the (capturing) default stream
    cudaEventRecord(ev_fork, 0);
    cudaStreamWaitEvent(s_kv, ev_fork, 0);
    cudaStreamWaitEvent(s_w,  ev_fork, 0);

    // --- side stream s_w: all weight transposes ---
    transpose_split_kernel<<<dim3(CV / 32, CV / 32), dim3(32, 8), 0, s_w>>>(wq, pwqhT, pwqlT, CV, CV);
    transpose_h_kernel<<<dim3(CV / 32, CV / 32), dim3(32, 8), 0, s_w>>>(wo, pwoT, CV, CV);
    transpose_h_kernel<<<dim3(CFF / 32, CV / 32), dim3(32, 8), 0, s_w>>>(w1, pw1T, CV, CFF);
    transpose_h_kernel<<<dim3(CV / 32, CFF / 32), dim3(32, 8), 0, s_w>>>(w2, pw2T, CFF, CV);
    cudaEventRecord(ev_w, s_w);

    // --- side stream s_kv: K/V projections + K l2norm + pad mask ---
    kv_sgemm_kernel<<<dim3(CV / GBN, (TROWS + GBM - 1) / GBM, 2), 256, 0, s_kv>>>(
        txt, wk, bk, pk, wv, bv, pv, TROWS, CV, CV);
    l2norm_kernel<<<TROWS, 256, 0, s_kv>>>(pk, TROWS * NH, nullptr, 0);
    padmask_kernel<<<TROWS, 128, 0, s_kv>>>(txt, ppad);
    cudaEventRecord(ev_kv, s_kv);

    // --- main stream: LN1 -> Q chain ---
    ln_kernel<<<NTOK, 128>>>(vis, ln1g, ln1b, px, pxh, pxl);

    cudaStreamWaitEvent(0, ev_w, 0);   // need wq transposes before qgemm
    qgemm_kernel<<<dim3(CV / 128, NTOK / 128), 256, QG_SMEM>>>(
        pxh, pxl, pwqhT, pwqlT, bq, pq, NTOK, CV, CV);
    l2norm_kernel<<<(NTOK * NH) / 8, 256>>>(pq, NTOK * NH, lsc, 1);

    cudaStreamWaitEvent(0, ev_kv, 0);  // need K/V + pad before attention
    attn_kernel<<<dim3(BQ * NH, NPIX / 64), 256>>>(pq, pk, pv, ppad, patth);

    // 5. O-proj (fp16 TC): y = x + alpha*(att@wo + bo)
    hgemm_kernel<2><<<dim3(CV / 128, NTOK / 128), 256, HGEMM_SMEM>>>(
        patth, pwoT, bo, px, alpha, py, NTOK, CV, CV);

    // 6. LN2 (fp32 + half)
    ln_kernel<<<NTOK, 128>>>(py, ln2g, ln2b, py2, py2h, nullptr);

    // 7. MLP (fp16 TC): h = half(gelu(y2@w1 + b1)); out = y2 + h@w2 + b2
    hgemm_kernel<1><<<dim3(CFF / 128, NTOK / 128), 256, HGEMM_SMEM>>>(
        py2h, pw1T, b1, nullptr, nullptr, phh, NTOK, CFF, CV);
    hgemm_kernel<3><<<dim3(CV / 128, NTOK / 128), 256, HGEMM_SMEM>>>(
        phh, pw2T, b2, py2, nullptr, out, NTOK, CV, CFF);
}